// round 13
// baseline (speedup 1.0000x reference)
#include <cuda_runtime.h>
#include <cuda_fp16.h>
#include <cuda_bf16.h>
#include <cstdint>

#define NODES   10000
#define EDGES   320000
#define HIDC    128
#define NGAUSS  50
#define NBLK    6

#define NTILE   32     // nodes per CTA in k_gemm0
#define FTILE   64     // nodes per CTA in fused GEMM kernel (512 threads)

#define GDELTA  (10.0f / 49.0f)
#define GCOEFF  (-0.5f / (GDELTA * GDELTA))

#define TROWS   3072                     // filter table rows
#define DMAX    8.66025404f              // max possible d (box 5^3)
#define TSCALE  ((TROWS - 1) / DMAX)
#define DSTEP   (DMAX / (TROWS - 1))

// ---------------- scratch (device globals; no runtime allocation) ----------
__device__ float  g_h[NODES * HIDC];
__device__ __align__(16) __half g_xh[NODES * HIDC];   // x in fp16 (message path)
__device__ float  g_agg[NODES * HIDC];

// transposed+swizzled node-GEMM weights: [0..5]=cl1[k], [6..11]=cl2[k], [12..17]=lw[k]
__device__ __align__(16) float g_wt[18][16384];

// CSR by target node + per-edge interp metadata
__device__ int  g_cnt[NODES];
__device__ int  g_rank[EDGES];
__device__ int  g_ptr[NODES + 1];
__device__ __align__(16) int4 g_meta[EDGES];   // {row, tbase, w0_bits, w1_bits}

// filter tables in fp16: W_k(d) on TROWS points, [TROWS][128] per block
__device__ __align__(16) __half g_tableh[NBLK][TROWS * HIDC];

// pre-split bf16 hi/lo weight images, padded row-major [ch][Kpad]
__device__ __align__(16) uint32_t g_w1h[NBLK][4608];
__device__ __align__(16) uint32_t g_w1l[NBLK][4608];
__device__ __align__(16) uint32_t g_w2h[NBLK][8704];
__device__ __align__(16) uint32_t g_w2l[NBLK][8704];

// ---------------- helpers ---------------------------------------------------
using ull = unsigned long long;

__device__ __forceinline__ uint32_t smem_u32(const void* p) {
    uint32_t a;
    asm("{ .reg .u64 t; cvta.to.shared.u64 t, %1; cvt.u32.u64 %0, t; }" : "=r"(a) : "l"(p));
    return a;
}
#define CP16(s, g) asm volatile("cp.async.cg.shared.global [%0], [%1], 16;" :: "r"(s), "l"(g))
#define CP_COMMIT() asm volatile("cp.async.commit_group;" ::: "memory")
#define CP_WAIT(n)  asm volatile("cp.async.wait_group %0;" :: "n"(n) : "memory")

__device__ __forceinline__ void ldsm_x4(uint32_t* r, uint32_t addr) {
    asm volatile("ldmatrix.sync.aligned.m8n8.x4.shared.b16 {%0,%1,%2,%3}, [%4];"
                 : "=r"(r[0]), "=r"(r[1]), "=r"(r[2]), "=r"(r[3]) : "r"(addr));
}
__device__ __forceinline__ void ldsm_x2(uint32_t* r, uint32_t addr) {
    asm volatile("ldmatrix.sync.aligned.m8n8.x2.shared.b16 {%0,%1}, [%2];"
                 : "=r"(r[0]), "=r"(r[1]) : "r"(addr));
}
__device__ __forceinline__ void mma_bf16(float* c, const uint32_t* a, const uint32_t* b) {
    asm volatile("mma.sync.aligned.m16n8k16.row.col.f32.bf16.bf16.f32 "
                 "{%0,%1,%2,%3}, {%4,%5,%6,%7}, {%8,%9}, {%0,%1,%2,%3};"
                 : "+f"(c[0]), "+f"(c[1]), "+f"(c[2]), "+f"(c[3])
                 : "r"(a[0]), "r"(a[1]), "r"(a[2]), "r"(a[3]), "r"(b[0]), "r"(b[1]));
}
__device__ __forceinline__ uint32_t bfpair(float f0, float f1) {
    uint32_t r;
    asm("cvt.rn.bf16x2.f32 %0, %1, %2;" : "=r"(r) : "f"(f1), "f"(f0));
    return r;
}
__device__ __forceinline__ void bfsplit(float f0, float f1, uint32_t& hi, uint32_t& lo) {
    hi = bfpair(f0, f1);
    float h0 = __uint_as_float(hi << 16);
    float h1 = __uint_as_float(hi & 0xFFFF0000u);
    lo = bfpair(f0 - h0, f1 - h1);
}
__device__ __forceinline__ float sspf(float v) {
    float t, u;
    asm("ex2.approx.f32 %0, %1;" : "=f"(t) : "f"(v * 1.4426950408889634f));
    asm("lg2.approx.f32 %0, %1;" : "=f"(u) : "f"(fmaf(0.5f, t, 0.5f)));
    return 0.6931471805599453f * u;
}
__device__ __forceinline__ ull pack2(float a, float b) {
    ull r; asm("mov.b64 %0, {%1, %2};" : "=l"(r) : "f"(a), "f"(b)); return r;
}
__device__ __forceinline__ void unpack2(ull v, float& a, float& b) {
    asm("mov.b64 {%0, %1}, %2;" : "=f"(a), "=f"(b) : "l"(v));
}
__device__ __forceinline__ ull fma2(ull a, ull b, ull c) {
    ull r; asm("fma.rn.f32x2 %0, %1, %2, %3;" : "=l"(r) : "l"(a), "l"(b), "l"(c));
    return r;
}

// ---------------- filter weight prep (split + pad + transpose) --------------
__global__ void k_wprep(const float* __restrict__ mw1, const float* __restrict__ mw2) {
    const int k = blockIdx.x;
    const float* w1 = mw1 + k * NGAUSS * HIDC;
    const float* w2 = mw2 + k * HIDC * HIDC;
    for (int i = threadIdx.x; i < 4608; i += blockDim.x) {
        int c = i / 36, kk = (i % 36) * 2;
        float v0 = (kk     < NGAUSS) ? w1[kk * HIDC + c]       : 0.f;
        float v1 = (kk + 1 < NGAUSS) ? w1[(kk + 1) * HIDC + c] : 0.f;
        uint32_t hi, lo; bfsplit(v0, v1, hi, lo);
        g_w1h[k][i] = hi; g_w1l[k][i] = lo;
    }
    for (int i = threadIdx.x; i < 8704; i += blockDim.x) {
        int c = i / 68, kk = (i % 68) * 2;
        float v0 = (kk     < HIDC) ? w2[kk * HIDC + c]       : 0.f;
        float v1 = (kk + 1 < HIDC) ? w2[(kk + 1) * HIDC + c] : 0.f;
        uint32_t hi, lo; bfsplit(v0, v1, hi, lo);
        g_w2h[k][i] = hi; g_w2l[k][i] = lo;
    }
}

// ---------------- node-GEMM weight transpose + chunk swizzle ----------------
// dst[f*128 + ((j ^ (f&31))<<2) + (c&3)] = src[c*128 + f], j = c>>2
__global__ void k_wtrans(const float* __restrict__ cl1, const float* __restrict__ cl2,
                         const float* __restrict__ lw) {
    const int m = blockIdx.x;   // 0..17
    const float* src = (m < 6) ? cl1 + m * 16384
                     : (m < 12) ? cl2 + (m - 6) * 16384
                                : lw + (m - 12) * 16384;
    float* dst = g_wt[m];
    for (int i = threadIdx.x; i < 16384; i += blockDim.x) {
        int c = i >> 7, f = i & 127;
        int j = c >> 2;
        dst[f * 128 + (((j ^ (f & 31)) << 2) | (c & 3))] = src[i];
    }
}

// ---------------- node embedding gather (+ zero CSR counters) ---------------
__global__ void k_embed(const int* __restrict__ z, const float* __restrict__ emb) {
    int i = blockIdx.x * blockDim.x + threadIdx.x;
    if (i < NODES) g_cnt[i] = 0;
    if (i >= NODES * HIDC) return;
    g_h[i] = emb[z[i >> 7] * HIDC + (i & 127)];
}

// ---------------- CSR build ---------------------------------------------------
__global__ void k_count(const int* __restrict__ col) {
    int e = blockIdx.x * blockDim.x + threadIdx.x;
    if (e >= EDGES) return;
    g_rank[e] = atomicAdd(&g_cnt[col[e]], 1);
}
__global__ void k_scan() {   // single block, 1024 threads, chunk=10
    __shared__ int s[1024];
    const int t = threadIdx.x;
    const int base = t * 10;
    int local[10];
    int sum = 0;
    #pragma unroll
    for (int i = 0; i < 10; i++) {
        int idx = base + i;
        local[i] = (idx < NODES) ? g_cnt[idx] : 0;
        sum += local[i];
    }
    s[t] = sum;
    __syncthreads();
    for (int off = 1; off < 1024; off <<= 1) {
        int v = (t >= off) ? s[t - off] : 0;
        __syncthreads();
        s[t] += v;
        __syncthreads();
    }
    int run = (t > 0) ? s[t - 1] : 0;   // exclusive prefix
    #pragma unroll
    for (int i = 0; i < 10; i++) {
        int idx = base + i;
        if (idx < NODES) { g_ptr[idx] = run; run += local[i]; }
    }
    if (t == 1023) g_ptr[NODES] = s[1023];
}
__global__ void k_fill(const float* __restrict__ pos,
                       const int* __restrict__ row, const int* __restrict__ col) {
    int e = blockIdx.x * blockDim.x + threadIdx.x;
    if (e >= EDGES) return;
    int r = row[e], c = col[e];
    float dx = pos[r * 3 + 0] - pos[c * 3 + 0];
    float dy = pos[r * 3 + 1] - pos[c * 3 + 1];
    float dz = pos[r * 3 + 2] - pos[c * 3 + 2];
    float d = sqrtf(dx * dx + dy * dy + dz * dz);
    float C = 0.5f * (cosf(d * (3.14159265358979323846f / 10.0f)) + 1.0f);
    int pos_ = g_ptr[c] + g_rank[e];
    float fidx = d * TSCALE;
    int tb = (int)fidx;
    if (tb > TROWS - 2) tb = TROWS - 2;
    float fr = fidx - (float)tb;
    int4 m;
    m.x = r;
    m.y = tb;
    m.z = __float_as_int((1.0f - fr) * C);
    m.w = __float_as_int(fr * C);
    g_meta[pos_] = m;
}

// ---------------- table build: MMA filter MLP on TROWS d-samples -------------
#define S_W1H 0
#define S_W1L 18432
#define S_W2H 36864
#define S_W2L 71680
#define S_AH  106496
#define S_AL  141312
#define FILT_SMEM 176128

__global__ void __launch_bounds__(256, 1)
k_tbuild(const float* __restrict__ mb1, const float* __restrict__ mb2) {
    extern __shared__ __align__(16) unsigned char sraw[];
    const uint32_t sb = smem_u32(sraw);
    const int tid  = threadIdx.x;
    const int wid  = tid >> 5;
    const int lan  = tid & 31;
    const int kblk = blockIdx.y;
    const int e0   = blockIdx.x * 128;
    const float* b1g = mb1 + kblk * HIDC;
    const float* b2g = mb2 + kblk * HIDC;

    {
        const int4* s1h = (const int4*)g_w1h[kblk];
        const int4* s1l = (const int4*)g_w1l[kblk];
        const int4* s2h = (const int4*)g_w2h[kblk];
        const int4* s2l = (const int4*)g_w2l[kblk];
        int4* d1h = (int4*)(sraw + S_W1H);
        int4* d1l = (int4*)(sraw + S_W1L);
        int4* d2h = (int4*)(sraw + S_W2H);
        int4* d2l = (int4*)(sraw + S_W2L);
        #pragma unroll 2
        for (int i = tid; i < 1152; i += 256) { d1h[i] = s1h[i]; d1l[i] = s1l[i]; }
        #pragma unroll 4
        for (int i = tid; i < 2176; i += 256) { d2h[i] = s2h[i]; d2l[i] = s2l[i]; }
    }

    for (int i = tid; i < 128 * 36; i += 256) {
        int e = i / 36, kk = (i % 36) * 2;
        float d = (float)(e0 + e) * DSTEP;
        float v0 = 0.f, v1 = 0.f;
        if (kk < NGAUSS)     { float dd = d - (float)kk * GDELTA;       v0 = __expf(GCOEFF * dd * dd); }
        if (kk + 1 < NGAUSS) { float dd = d - (float)(kk + 1) * GDELTA; v1 = __expf(GCOEFF * dd * dd); }
        uint32_t hi, lo; bfsplit(v0, v1, hi, lo);
        *(uint32_t*)(sraw + S_AH + e * 144 + kk * 2) = hi;
        *(uint32_t*)(sraw + S_AL + e * 144 + kk * 2) = lo;
    }
    __syncthreads();

    const uint32_t aoff1 = (lan & 15) * 144 + (lan >> 4) * 16;
    const uint32_t boff1 = (wid * 16 + (lan & 7)) * 144 + ((lan >> 3) & 1) * 16;
    const uint32_t aoff2 = (lan & 15) * 272 + (lan >> 4) * 16;
    const uint32_t boff2 = (wid * 16 + (lan & 7)) * 272 + ((lan >> 3) & 1) * 16;

    float acc[8][2][4];

    // layer 1
    #pragma unroll
    for (int mt = 0; mt < 8; mt++)
        #pragma unroll
        for (int nt = 0; nt < 2; nt++)
            #pragma unroll
            for (int i = 0; i < 4; i++) acc[mt][nt][i] = 0.f;
    {
        const uint32_t ab[3] = { sb + S_AH + aoff1, sb + S_AH + aoff1, sb + S_AL + aoff1 };
        const uint32_t bb[3] = { sb + S_W1H + boff1, sb + S_W1L + boff1, sb + S_W1H + boff1 };
        #pragma unroll 1
        for (int t = 0; t < 3; t++) {
            #pragma unroll 1
            for (int ks = 0; ks < 4; ks++) {
                uint32_t bf0[2], bf1[2];
                ldsm_x2(bf0, bb[t] + ks * 32);
                ldsm_x2(bf1, bb[t] + 8 * 144 + ks * 32);
                #pragma unroll
                for (int mt = 0; mt < 8; mt++) {
                    uint32_t af[4];
                    ldsm_x4(af, ab[t] + mt * (16 * 144) + ks * 32);
                    mma_bf16(acc[mt][0], af, bf0);
                    mma_bf16(acc[mt][1], af, bf1);
                }
            }
        }
    }
    __syncthreads();

    // epilogue 1: ssp(acc + b1) -> A2 hi/lo [128][136]
    {
        const int ch0 = wid * 16 + (lan & 3) * 2;
        const float bA0 = b1g[ch0],     bA1 = b1g[ch0 + 1];
        const float bA2 = b1g[ch0 + 8], bA3 = b1g[ch0 + 9];
        #pragma unroll
        for (int mt = 0; mt < 8; mt++) {
            int er = mt * 16 + (lan >> 2);
            uint32_t hi, lo;
            float v0 = sspf(acc[mt][0][0] + bA0), v1 = sspf(acc[mt][0][1] + bA1);
            bfsplit(v0, v1, hi, lo);
            *(uint32_t*)(sraw + S_AH + er * 272 + ch0 * 2) = hi;
            *(uint32_t*)(sraw + S_AL + er * 272 + ch0 * 2) = lo;
            float v2 = sspf(acc[mt][0][2] + bA0), v3 = sspf(acc[mt][0][3] + bA1);
            bfsplit(v2, v3, hi, lo);
            *(uint32_t*)(sraw + S_AH + (er + 8) * 272 + ch0 * 2) = hi;
            *(uint32_t*)(sraw + S_AL + (er + 8) * 272 + ch0 * 2) = lo;
            float v4 = sspf(acc[mt][1][0] + bA2), v5 = sspf(acc[mt][1][1] + bA3);
            bfsplit(v4, v5, hi, lo);
            *(uint32_t*)(sraw + S_AH + er * 272 + (ch0 + 8) * 2) = hi;
            *(uint32_t*)(sraw + S_AL + er * 272 + (ch0 + 8) * 2) = lo;
            float v6 = sspf(acc[mt][1][2] + bA2), v7 = sspf(acc[mt][1][3] + bA3);
            bfsplit(v6, v7, hi, lo);
            *(uint32_t*)(sraw + S_AH + (er + 8) * 272 + (ch0 + 8) * 2) = hi;
            *(uint32_t*)(sraw + S_AL + (er + 8) * 272 + (ch0 + 8) * 2) = lo;
        }
    }
    __syncthreads();

    // layer 2
    #pragma unroll
    for (int mt = 0; mt < 8; mt++)
        #pragma unroll
        for (int nt = 0; nt < 2; nt++)
            #pragma unroll
            for (int i = 0; i < 4; i++) acc[mt][nt][i] = 0.f;
    {
        const uint32_t ab[3] = { sb + S_AH + aoff2, sb + S_AH + aoff2, sb + S_AL + aoff2 };
        const uint32_t bb[3] = { sb + S_W2H + boff2, sb + S_W2L + boff2, sb + S_W2H + boff2 };
        #pragma unroll 1
        for (int t = 0; t < 3; t++) {
            #pragma unroll 1
            for (int ks = 0; ks < 8; ks++) {
                uint32_t bf0[2], bf1[2];
                ldsm_x2(bf0, bb[t] + ks * 32);
                ldsm_x2(bf1, bb[t] + 8 * 272 + ks * 32);
                #pragma unroll
                for (int mt = 0; mt < 8; mt++) {
                    uint32_t af[4];
                    ldsm_x4(af, ab[t] + mt * (16 * 272) + ks * 32);
                    mma_bf16(acc[mt][0], af, bf0);
                    mma_bf16(acc[mt][1], af, bf1);
                }
            }
        }
    }

    // epilogue 2: table[row][ch] = acc + b2  (fp16 table)
    {
        __half2* tbl = (__half2*)g_tableh[kblk];
        const int ch0 = wid * 16 + (lan & 3) * 2;   // even
        const int cp  = ch0 >> 1;
        const float bB0 = b2g[ch0],     bB1 = b2g[ch0 + 1];
        const float bB2 = b2g[ch0 + 8], bB3 = b2g[ch0 + 9];
        #pragma unroll
        for (int mt = 0; mt < 8; mt++) {
            int r0 = e0 + mt * 16 + (lan >> 2);
            int r1 = r0 + 8;
            tbl[r0 * 64 + cp]     = __floats2half2_rn(acc[mt][0][0] + bB0, acc[mt][0][1] + bB1);
            tbl[r1 * 64 + cp]     = __floats2half2_rn(acc[mt][0][2] + bB0, acc[mt][0][3] + bB1);
            tbl[r0 * 64 + cp + 4] = __floats2half2_rn(acc[mt][1][0] + bB2, acc[mt][1][1] + bB3);
            tbl[r1 * 64 + cp + 4] = __floats2half2_rn(acc[mt][1][2] + bB2, acc[mt][1][3] + bB3);
        }
    }
}

// ---------------- message + aggregate: CSR gather, fp16 table lerp ----------
__global__ void __launch_bounds__(256)
k_msg(int kblk) {
    const int wid = threadIdx.x >> 5;
    const int lan = threadIdx.x & 31;
    const int n = blockIdx.x * 8 + wid;
    if (n >= NODES) return;
    const int s = g_ptr[n], e = g_ptr[n + 1];
    const uint2* __restrict__ T = (const uint2*)g_tableh[kblk];   // 32 uint2/row
    const uint2* __restrict__ X = (const uint2*)g_xh;
    float4 acc = make_float4(0.f, 0.f, 0.f, 0.f);
    #pragma unroll 2
    for (int j = s; j < e; j++) {
        const int4 m = __ldg(&g_meta[j]);
        const float w0 = __int_as_float(m.z);
        const float w1 = __int_as_float(m.w);
        const uint2 xr = X[m.x * 32 + lan];
        const uint2 t0 = T[m.y * 32 + lan];
        const uint2 t1 = T[m.y * 32 + 32 + lan];
        float2 xa = __half22float2(*(const __half2*)&xr.x);
        float2 xb = __half22float2(*(const __half2*)&xr.y);
        float2 a0 = __half22float2(*(const __half2*)&t0.x);
        float2 a1 = __half22float2(*(const __half2*)&t0.y);
        float2 b0 = __half22float2(*(const __half2*)&t1.x);
        float2 b1 = __half22float2(*(const __half2*)&t1.y);
        acc.x += xa.x * (a0.x * w0 + b0.x * w1);
        acc.y += xa.y * (a0.y * w0 + b0.y * w1);
        acc.z += xb.x * (a1.x * w0 + b1.x * w1);
        acc.w += xb.y * (a1.y * w0 + b1.y * w1);
    }
    ((float4*)g_agg)[n * 32 + lan] = acc;
}

// swizzled weight fetch: Wt row f, cols c..c+3 (c % 4 == 0)
__device__ __forceinline__ float4 wld(const float* Ws, int f, int c) {
    int j = c >> 2;
    return *(const float4*)&Ws[f * 128 + (((j ^ (f & 31)) << 2))];
}

// ---------------- first node GEMM: xh = h @ cl1[0] ---------------------------
// 256 threads, NTILE=32: f2 = tid&63 (ch f2, f2+64), grp = tid>>6 (4 x 8 nodes)
#define G0_SMEM ((16384 + NTILE * HIDC) * 4)
__global__ void __launch_bounds__(256)
k_gemm0() {
    extern __shared__ __align__(16) unsigned char sraw[];
    float* Ws  = (float*)sraw;                // 64 KB (swizzled)
    float* ins = Ws + 16384;                  // 16 KB
    const uint32_t sW = smem_u32(Ws);
    const uint32_t sD = smem_u32(ins);

    const int tid = threadIdx.x;
    const int f2  = tid & 63;
    const int grp = tid >> 6;
    const int n0  = blockIdx.x * NTILE;
    const int nb  = grp * 8;

    {
        uint64_t gw = __cvta_generic_to_global(g_wt[0]);
        #pragma unroll
        for (int i = tid; i < 4096; i += 256) CP16(sW + i * 16, gw + i * 16);
        uint64_t ga = __cvta_generic_to_global(g_h);
        #pragma unroll
        for (int i = tid; i < 1024; i += 256) {
            int n = n0 + (i >> 5);
            int nc = (n < NODES) ? n : NODES - 1;
            CP16(sD + i * 16, ga + (uint64_t)(nc * 32 + (i & 31)) * 16);
        }
    }
    CP_COMMIT();
    CP_WAIT(0);
    __syncthreads();

    ull acc0[8], acc1[8];
    #pragma unroll
    for (int e = 0; e < 8; e++) { acc0[e] = pack2(0.f, 0.f); acc1[e] = pack2(0.f, 0.f); }

    #pragma unroll 1
    for (int c = 0; c < HIDC; c += 4) {
        float4 wa = wld(Ws, f2, c);
        float4 wb = wld(Ws, f2 + 64, c);
        ull wa01 = pack2(wa.x, wa.y), wa23 = pack2(wa.z, wa.w);
        ull wb01 = pack2(wb.x, wb.y), wb23 = pack2(wb.z, wb.w);
        #pragma unroll
        for (int e = 0; e < 8; e++) {
            ulonglong2 hv = *(const ulonglong2*)&ins[(nb + e) * HIDC + c];
            acc0[e] = fma2(hv.x, wa01, acc0[e]);
            acc0[e] = fma2(hv.y, wa23, acc0[e]);
            acc1[e] = fma2(hv.x, wb01, acc1[e]);
            acc1[e] = fma2(hv.y, wb23, acc1[e]);
        }
    }

    #pragma unroll
    for (int e = 0; e < 8; e++) {
        int n = n0 + nb + e;
        if (n < NODES) {
            float a, b;
            unpack2(acc0[e], a, b);
            g_xh[n * HIDC + f2]      = __float2half(a + b);
            unpack2(acc1[e], a, b);
            g_xh[n * HIDC + f2 + 64] = __float2half(a + b);
        }
    }
}

// ------ fused node GEMMs, cp.async double-buffered swizzled weights ----------
// 512 threads, FTILE=64. f2 = tid&63 owns {f2, f2+64}; grp = tid>>6 owns 8 nodes.
//   A: mid = ssp(agg @ W2 + b2)   [W0 = g_wt[6+k]]   (prefetch g_wt[12+k] -> W1)
//   B: h  += mid @ Wl + bl        [W1]               (prefetch g_wt[1+k]  -> W0)
//   C: xh  = h_new @ Wc (fp16)    [W0]
#define GF_SMEM ((16384 * 2 + FTILE * HIDC) * 4)   // 163840 B

template <bool DO_C>
__global__ void __launch_bounds__(512, 1)
k_gfused(int kblk, const float* __restrict__ b2v, const float* __restrict__ blv) {
    extern __shared__ __align__(16) unsigned char sraw[];
    float* W0   = (float*)sraw;                     // 64 KB
    float* W1   = W0 + 16384;                       // 64 KB
    float* data = W1 + 16384;                       // 32 KB
    const uint32_t sW0 = smem_u32(W0);
    const uint32_t sW1 = smem_u32(W1);
    const uint32_t sD  = smem_u32(data);

    const int tid = threadIdx.x;
    const int f2  = tid & 63;
    const int grp = tid >> 6;       // 0..7
    const int n0  = blockIdx.x * FTILE;
    const int nb  = grp * 8;

    // group 0: W2 + agg tile
    {
        uint64_t gw = __cvta_generic_to_global(g_wt[6 + kblk]);
        #pragma unroll
        for (int i = tid; i < 4096; i += 512) CP16(sW0 + i * 16, gw + i * 16);
        uint64_t ga = __cvta_generic_to_global(g_agg);
        #pragma unroll
        for (int i = tid; i < 2048; i += 512) {
            int n = n0 + (i >> 5);
            int nc = (n < NODES) ? n : NODES - 1;
            CP16(sD + i * 16, ga + (uint64_t)(nc * 32 + (i & 31)) * 16);
        }
    }
    CP_COMMIT();
    // group 1: Wl
    {
        uint64_t gw = __cvta_generic_to_global(g_wt[12 + kblk]);
        #pragma unroll
        for (int i = tid; i < 4096; i += 512) CP16(sW1 + i * 16, gw + i * 16);
    }
    CP_COMMIT();

    const float b2a = b2v[f2],      b2b = b2v[f2 + 64];
    const float bla = blv[f2],      blb = blv[f2 + 64];

    CP_WAIT(1);          // group 0 (W2 + agg) complete
    __syncthreads();

    // ---- phase A: mid = ssp(agg @ W2 + b2) ----
    float mida[8], midb[8];
    {
        ull acc0[8], acc1[8];
        #pragma unroll
        for (int e = 0; e < 8; e++) { acc0[e] = pack2(b2a, 0.f); acc1[e] = pack2(b2b, 0.f); }
        #pragma unroll 1
        for (int c = 0; c < HIDC; c += 4) {
            float4 wa = wld(W0, f2, c);
            float4 wb = wld(W0, f2 + 64, c);
            ull wa01 = pack2(wa.x, wa.y), wa23 = pack2(wa.z, wa.w);
            ull wb01 = pack2(wb.x, wb.y), wb23 = pack2(wb.z, wb.w);
            #pragma unroll
            for (int e = 0; e < 8; e++) {
                ulonglong2 hv = *(const ulonglong2*)&data[(nb + e) * HIDC + c];
                acc0[e] = fma2(hv.x, wa01, acc0[e]);
                acc0[e] = fma2(hv.y, wa23, acc0[e]);
                acc1[e] = fma2(hv.x, wb01, acc1[e]);
                acc1[e] = fma2(hv.y, wb23, acc1[e]);
            }
        }
        #pragma unroll
        for (int e = 0; e < 8; e++) {
            float a, b;
            unpack2(acc0[e], a, b); mida[e] = sspf(a + b);
            unpack2(acc1[e], a, b); midb[e] = sspf(a + b);
        }
    }
    __syncthreads();    // reads of W0/data done

    // data = mid ; prefetch Wc -> W0
    #pragma unroll
    for (int e = 0; e < 8; e++) {
        data[(nb + e) * HIDC + f2]      = mida[e];
        data[(nb + e) * HIDC + f2 + 64] = midb[e];
    }
    if (DO_C) {
        uint64_t gw = __cvta_generic_to_global(g_wt[1 + kblk]);
        #pragma unroll
        for (int i = tid; i < 4096; i += 512) CP16(sW0 + i * 16, gw + i * 16);
        CP_COMMIT();
        CP_WAIT(1);      // Wl complete
    } else {
        CP_WAIT(0);      // Wl complete
    }
    __syncthreads();

    // ---- phase B: h_new = h + mid @ Wl + bl ----
    float hna[8], hnb[8];
    {
        ull acc0[8], acc1[8];
        #pragma unroll
        for (int e = 0; e < 8; e++) { acc0[e] = pack2(bla, 0.f); acc1[e] = pack2(blb, 0.f); }
        #pragma unroll 1
        for (int c = 0; c < HIDC; c += 4) {
            float4 wa = wld(W1, f2, c);
            float4 wb = wld(W1, f2 + 64, c);
            ull wa01 = pack2(wa.x, wa.y), wa23 = pack2(wa.z, wa.w);
            ull wb01 = pack2(wb.x, wb.y), wb23 = pack2(wb.z, wb.w);
            #pragma unroll
            for (int e = 0; e < 8; e++) {
                ulonglong2 hv = *(const ulonglong2*)&data[(nb + e) * HIDC + c];
                acc0[e] = fma2(hv.x, wa01, acc0[e]);
                acc0[e] = fma2(hv.y, wa23, acc0[e]);
                acc1[e] = fma2(hv.x, wb01, acc1[e]);
                acc1[e] = fma2(hv.y, wb23, acc1[e]);
            }
        }
        #pragma unroll
        for (int e = 0; e < 8; e++) {
            int n = n0 + nb + e;
            float a, b;
            unpack2(acc0[e], a, b);
            float h0 = (n < NODES) ? g_h[n * HIDC + f2] : 0.f;
            hna[e] = h0 + a + b;
            unpack2(acc1[e], a, b);
            float h1 = (n < NODES) ? g_h[n * HIDC + f2 + 64] : 0.f;
            hnb[e] = h1 + a + b;
            if (n < NODES) {
                g_h[n * HIDC + f2]      = hna[e];
                g_h[n * HIDC + f2 + 64] = hnb[e];
            }
        }
    }
    if (!DO_C) return;

    __syncthreads();    // phase B reads of data done

    // data = h_new
    #pragma unroll
    for (int e = 0; e < 8; e++) {
        data[(nb + e) * HIDC + f2]      = hna[e];
        data[(nb + e) * HIDC + f2 + 64] = hnb[e];
    }
    CP_WAIT(0);          // Wc complete
    __syncthreads();

    // ---- phase C: xh = h_new @ Wc (fp16) ----
    {
        ull acc0[8], acc1[8];
        #pragma unroll
        for (int e = 0; e < 8; e++) { acc0[e] = pack2(0.f, 0.f); acc1[e] = pack2(0.f, 0.f); }
        #pragma unroll 1
        for (int c = 0; c < HIDC; c += 4) {
            float4 wa = wld(W0, f2, c);
            float4 wb = wld(W0, f2 + 64, c);
            ull wa01 = pack2(wa.x, wa.y), wa23 = pack2(wa.z, wa.w);
            ull wb01 = pack2(wb.x, wb.y), wb23 = pack2(wb.z, wb.w);
            #pragma unroll
            for (int e = 0; e < 8; e++) {
                ulonglong2 hv = *(const ulonglong2*)&data[(nb + e) * HIDC + c];
                acc0[e] = fma2(hv.x, wa01, acc0[e]);
                acc0[e] = fma2(hv.y, wa23, acc0[e]);
                acc1[e] = fma2(hv.x, wb01, acc1[e]);
                acc1[e] = fma2(hv.y, wb23, acc1[e]);
            }
        }
        #pragma unroll
        for (int e = 0; e < 8; e++) {
            int n = n0 + nb + e;
            if (n < NODES) {
                float a, b;
                unpack2(acc0[e], a, b);
                g_xh[n * HIDC + f2]      = __float2half(a + b);
                unpack2(acc1[e], a, b);
                g_xh[n * HIDC + f2 + 64] = __float2half(a + b);
            }
        }
    }
}

// ---------------- output head ------------------------------------------------
__global__ void k_out(const float* __restrict__ w1, const float* __restrict__ b1,
                      const float* __restrict__ w2, const float* __restrict__ b2,
                      float* __restrict__ out) {
    __shared__ float hrow[HIDC];
    __shared__ float partial[2];
    const int n = blockIdx.x, j = threadIdx.x;   // blockDim = 64
    hrow[j]      = g_h[n * HIDC + j];
    hrow[j + 64] = g_h[n * HIDC + 64 + j];
    __syncthreads();
    float acc = b1[j];
    #pragma unroll 8
    for (int c = 0; c < HIDC; c++) acc += hrow[c] * w1[c * 64 + j];
    float s = sspf(acc) * w2[j];
    #pragma unroll
    for (int o = 16; o > 0; o >>= 1) s += __shfl_down_sync(0xffffffffu, s, o);
    if ((j & 31) == 0) partial[j >> 5] = s;
    __syncthreads();
    if (j == 0) out[n] = partial[0] + partial[1] + b2[0];
}

// ---------------- launcher ---------------------------------------------------
extern "C" void kernel_launch(void* const* d_in, const int* in_sizes, int n_in,
                              void* d_out, int out_size) {
    const int*   z    = (const int*)d_in[0];
    const float* pos  = (const float*)d_in[1];
    const int*   ei   = (const int*)d_in[2];
    const float* emb  = (const float*)d_in[3];
    const float* mw1  = (const float*)d_in[4];
    const float* mb1  = (const float*)d_in[5];
    const float* mw2  = (const float*)d_in[6];
    const float* mb2  = (const float*)d_in[7];
    const float* cl1  = (const float*)d_in[8];
    const float* cl2  = (const float*)d_in[9];
    const float* cl2b = (const float*)d_in[10];
    const float* lw   = (const float*)d_in[11];
    const float* lb   = (const float*)d_in[12];
    const float* ow1  = (const float*)d_in[13];
    const float* ob1  = (const float*)d_in[14];
    const float* ow2  = (const float*)d_in[15];
    const float* ob2  = (const float*)d_in[16];
    float* out = (float*)d_out;

    const int* row = ei;
    const int* col = ei + EDGES;

    cudaFuncSetAttribute(k_tbuild, cudaFuncAttributeMaxDynamicSharedMemorySize, FILT_SMEM);
    cudaFuncSetAttribute(k_gemm0,  cudaFuncAttributeMaxDynamicSharedMemorySize, G0_SMEM);
    cudaFuncSetAttribute(k_gfused<true>,  cudaFuncAttributeMaxDynamicSharedMemorySize, GF_SMEM);
    cudaFuncSetAttribute(k_gfused<false>, cudaFuncAttributeMaxDynamicSharedMemorySize, GF_SMEM);

    // one-time (per launch) prep
    k_wprep<<<NBLK, 256>>>(mw1, mw2);
    k_wtrans<<<18, 256>>>(cl1, cl2, lw);
    k_embed<<<(NODES * HIDC + 255) / 256, 256>>>(z, emb);
    k_count<<<(EDGES + 255) / 256, 256>>>(col);
    k_scan<<<1, 1024>>>();
    k_fill<<<(EDGES + 255) / 256, 256>>>(pos, row, col);
    {
        dim3 tg(TROWS / 128, NBLK);
        k_tbuild<<<tg, 256, FILT_SMEM>>>(mb1, mb2);
    }

    const int g0grid = (NODES + NTILE - 1) / NTILE;
    const int gfgrid = (NODES + FTILE - 1) / FTILE;
    const int mgrid  = (NODES + 7) / 8;

    k_gemm0<<<g0grid, 256, G0_SMEM>>>();

    for (int k = 0; k < NBLK; k++) {
        k_msg<<<mgrid, 256>>>(k);
        if (k < NBLK - 1) {
            k_gfused<true><<<gfgrid, 512, GF_SMEM>>>(k, cl2b + k * HIDC, lb + k * HIDC);
        } else {
            k_gfused<false><<<gfgrid, 512, GF_SMEM>>>(k, cl2b + k * HIDC, lb + k * HIDC);
        }
    }

    k_out<<<NODES, 64>>>(ow1, ob1, ow2, ob2, out);
}

// round 14
// speedup vs baseline: 1.3597x; 1.3597x over previous
#include <cuda_runtime.h>
#include <cuda_fp16.h>
#include <cuda_bf16.h>
#include <cstdint>

#define NODES   10000
#define EDGES   320000
#define HIDC    128
#define NGAUSS  50
#define NBLK    6

#define NTILE   32     // nodes per CTA in k_gemm0
#define NPG     16

#define NPC     72     // nodes per CTA in fused GEMM kernel (512 thr, 8 grp x 9)
#define GNP     9      // nodes per thread-group

#define GDELTA  (10.0f / 49.0f)
#define GCOEFF  (-0.5f / (GDELTA * GDELTA))

#define TROWS   3072                     // filter table rows
#define DMAX    8.66025404f              // max possible d (box 5^3)
#define TSCALE  ((TROWS - 1) / DMAX)
#define DSTEP   (DMAX / (TROWS - 1))

// ---------------- scratch (device globals; no runtime allocation) ----------
__device__ float  g_h[NODES * HIDC];
__device__ __align__(16) __half g_xh[NODES * HIDC];   // x in fp16 (message path)
__device__ float  g_agg[NODES * HIDC];

// CSR by target node + per-edge interp metadata
__device__ int  g_cnt[NODES];
__device__ int  g_rank[EDGES];
__device__ int  g_ptr[NODES + 1];
__device__ __align__(16) int4 g_meta[EDGES];   // {row, tbase, w0_bits, w1_bits}

// filter tables in fp16: W_k(d) on TROWS points, [TROWS][128] per block
__device__ __align__(16) __half g_tableh[NBLK][TROWS * HIDC];

// pre-split bf16 hi/lo weight images, padded row-major [ch][Kpad]
__device__ __align__(16) uint32_t g_w1h[NBLK][4608];
__device__ __align__(16) uint32_t g_w1l[NBLK][4608];
__device__ __align__(16) uint32_t g_w2h[NBLK][8704];
__device__ __align__(16) uint32_t g_w2l[NBLK][8704];

// ---------------- helpers ---------------------------------------------------
using ull = unsigned long long;

__device__ __forceinline__ uint32_t smem_u32(const void* p) {
    uint32_t a;
    asm("{ .reg .u64 t; cvta.to.shared.u64 t, %1; cvt.u32.u64 %0, t; }" : "=r"(a) : "l"(p));
    return a;
}
#define CP16(s, g) asm volatile("cp.async.cg.shared.global [%0], [%1], 16;" :: "r"(s), "l"(g))
#define CP_COMMIT() asm volatile("cp.async.commit_group;" ::: "memory")
#define CP_WAIT(n)  asm volatile("cp.async.wait_group %0;" :: "n"(n) : "memory")

__device__ __forceinline__ void ldsm_x4(uint32_t* r, uint32_t addr) {
    asm volatile("ldmatrix.sync.aligned.m8n8.x4.shared.b16 {%0,%1,%2,%3}, [%4];"
                 : "=r"(r[0]), "=r"(r[1]), "=r"(r[2]), "=r"(r[3]) : "r"(addr));
}
__device__ __forceinline__ void ldsm_x2(uint32_t* r, uint32_t addr) {
    asm volatile("ldmatrix.sync.aligned.m8n8.x2.shared.b16 {%0,%1}, [%2];"
                 : "=r"(r[0]), "=r"(r[1]) : "r"(addr));
}
__device__ __forceinline__ void mma_bf16(float* c, const uint32_t* a, const uint32_t* b) {
    asm volatile("mma.sync.aligned.m16n8k16.row.col.f32.bf16.bf16.f32 "
                 "{%0,%1,%2,%3}, {%4,%5,%6,%7}, {%8,%9}, {%0,%1,%2,%3};"
                 : "+f"(c[0]), "+f"(c[1]), "+f"(c[2]), "+f"(c[3])
                 : "r"(a[0]), "r"(a[1]), "r"(a[2]), "r"(a[3]), "r"(b[0]), "r"(b[1]));
}
__device__ __forceinline__ uint32_t bfpair(float f0, float f1) {
    uint32_t r;
    asm("cvt.rn.bf16x2.f32 %0, %1, %2;" : "=r"(r) : "f"(f1), "f"(f0));
    return r;
}
__device__ __forceinline__ void bfsplit(float f0, float f1, uint32_t& hi, uint32_t& lo) {
    hi = bfpair(f0, f1);
    float h0 = __uint_as_float(hi << 16);
    float h1 = __uint_as_float(hi & 0xFFFF0000u);
    lo = bfpair(f0 - h0, f1 - h1);
}
__device__ __forceinline__ float sspf(float v) {
    float t, u;
    asm("ex2.approx.f32 %0, %1;" : "=f"(t) : "f"(v * 1.4426950408889634f));
    asm("lg2.approx.f32 %0, %1;" : "=f"(u) : "f"(fmaf(0.5f, t, 0.5f)));
    return 0.6931471805599453f * u;
}
__device__ __forceinline__ ull pack2(float a, float b) {
    ull r; asm("mov.b64 %0, {%1, %2};" : "=l"(r) : "f"(a), "f"(b)); return r;
}
__device__ __forceinline__ void unpack2(ull v, float& a, float& b) {
    asm("mov.b64 {%0, %1}, %2;" : "=f"(a), "=f"(b) : "l"(v));
}
__device__ __forceinline__ ull fma2(ull a, ull b, ull c) {
    ull r; asm("fma.rn.f32x2 %0, %1, %2, %3;" : "=l"(r) : "l"(a), "l"(b), "l"(c));
    return r;
}

// ---------------- weight prep (split + pad + transpose) + zero CSR counters -
__global__ void k_wprep(const float* __restrict__ mw1, const float* __restrict__ mw2) {
    const int k = blockIdx.x;
    // zero CSR counters (strictly precedes k_embed's atomics)
    for (int i = blockIdx.x * blockDim.x + threadIdx.x; i < NODES; i += gridDim.x * blockDim.x)
        g_cnt[i] = 0;
    const float* w1 = mw1 + k * NGAUSS * HIDC;
    const float* w2 = mw2 + k * HIDC * HIDC;
    for (int i = threadIdx.x; i < 4608; i += blockDim.x) {
        int c = i / 36, kk = (i % 36) * 2;
        float v0 = (kk     < NGAUSS) ? w1[kk * HIDC + c]       : 0.f;
        float v1 = (kk + 1 < NGAUSS) ? w1[(kk + 1) * HIDC + c] : 0.f;
        uint32_t hi, lo; bfsplit(v0, v1, hi, lo);
        g_w1h[k][i] = hi; g_w1l[k][i] = lo;
    }
    for (int i = threadIdx.x; i < 8704; i += blockDim.x) {
        int c = i / 68, kk = (i % 68) * 2;
        float v0 = (kk     < HIDC) ? w2[kk * HIDC + c]       : 0.f;
        float v1 = (kk + 1 < HIDC) ? w2[(kk + 1) * HIDC + c] : 0.f;
        uint32_t hi, lo; bfsplit(v0, v1, hi, lo);
        g_w2h[k][i] = hi; g_w2l[k][i] = lo;
    }
}

// ---------------- embedding gather + CSR count (merged) ----------------------
__global__ void k_embed(const int* __restrict__ z, const float* __restrict__ emb,
                        const int* __restrict__ col) {
    int i = blockIdx.x * blockDim.x + threadIdx.x;
    if (i < EDGES) g_rank[i] = atomicAdd(&g_cnt[col[i]], 1);
    if (i >= NODES * HIDC) return;
    g_h[i] = emb[z[i >> 7] * HIDC + (i & 127)];
}

// ---------------- CSR scan ----------------------------------------------------
__global__ void k_scan() {   // single block, 1024 threads, chunk=10
    __shared__ int s[1024];
    const int t = threadIdx.x;
    const int base = t * 10;
    int local[10];
    int sum = 0;
    #pragma unroll
    for (int i = 0; i < 10; i++) {
        int idx = base + i;
        local[i] = (idx < NODES) ? g_cnt[idx] : 0;
        sum += local[i];
    }
    s[t] = sum;
    __syncthreads();
    for (int off = 1; off < 1024; off <<= 1) {
        int v = (t >= off) ? s[t - off] : 0;
        __syncthreads();
        s[t] += v;
        __syncthreads();
    }
    int run = (t > 0) ? s[t - 1] : 0;   // exclusive prefix
    #pragma unroll
    for (int i = 0; i < 10; i++) {
        int idx = base + i;
        if (idx < NODES) { g_ptr[idx] = run; run += local[i]; }
    }
    if (t == 1023) g_ptr[NODES] = s[1023];
}
__global__ void k_fill(const float* __restrict__ pos,
                       const int* __restrict__ row, const int* __restrict__ col) {
    int e = blockIdx.x * blockDim.x + threadIdx.x;
    if (e >= EDGES) return;
    int r = row[e], c = col[e];
    float dx = pos[r * 3 + 0] - pos[c * 3 + 0];
    float dy = pos[r * 3 + 1] - pos[c * 3 + 1];
    float dz = pos[r * 3 + 2] - pos[c * 3 + 2];
    float d = sqrtf(dx * dx + dy * dy + dz * dz);
    float C = 0.5f * (cosf(d * (3.14159265358979323846f / 10.0f)) + 1.0f);
    int pos_ = g_ptr[c] + g_rank[e];
    float fidx = d * TSCALE;
    int tb = (int)fidx;
    if (tb > TROWS - 2) tb = TROWS - 2;
    float fr = fidx - (float)tb;
    int4 m;
    m.x = r;
    m.y = tb;
    m.z = __float_as_int((1.0f - fr) * C);
    m.w = __float_as_int(fr * C);
    g_meta[pos_] = m;
}

// ---------------- table build: MMA filter MLP on TROWS d-samples -------------
#define S_W1H 0
#define S_W1L 18432
#define S_W2H 36864
#define S_W2L 71680
#define S_AH  106496
#define S_AL  141312
#define FILT_SMEM 176128

__global__ void __launch_bounds__(256, 1)
k_tbuild(const float* __restrict__ mb1, const float* __restrict__ mb2) {
    extern __shared__ __align__(16) unsigned char sraw[];
    const uint32_t sb = smem_u32(sraw);
    const int tid  = threadIdx.x;
    const int wid  = tid >> 5;
    const int lan  = tid & 31;
    const int kblk = blockIdx.y;
    const int e0   = blockIdx.x * 128;
    const float* b1g = mb1 + kblk * HIDC;
    const float* b2g = mb2 + kblk * HIDC;

    {
        const int4* s1h = (const int4*)g_w1h[kblk];
        const int4* s1l = (const int4*)g_w1l[kblk];
        const int4* s2h = (const int4*)g_w2h[kblk];
        const int4* s2l = (const int4*)g_w2l[kblk];
        int4* d1h = (int4*)(sraw + S_W1H);
        int4* d1l = (int4*)(sraw + S_W1L);
        int4* d2h = (int4*)(sraw + S_W2H);
        int4* d2l = (int4*)(sraw + S_W2L);
        #pragma unroll 2
        for (int i = tid; i < 1152; i += 256) { d1h[i] = s1h[i]; d1l[i] = s1l[i]; }
        #pragma unroll 4
        for (int i = tid; i < 2176; i += 256) { d2h[i] = s2h[i]; d2l[i] = s2l[i]; }
    }

    for (int i = tid; i < 128 * 36; i += 256) {
        int e = i / 36, kk = (i % 36) * 2;
        float d = (float)(e0 + e) * DSTEP;
        float v0 = 0.f, v1 = 0.f;
        if (kk < NGAUSS)     { float dd = d - (float)kk * GDELTA;       v0 = __expf(GCOEFF * dd * dd); }
        if (kk + 1 < NGAUSS) { float dd = d - (float)(kk + 1) * GDELTA; v1 = __expf(GCOEFF * dd * dd); }
        uint32_t hi, lo; bfsplit(v0, v1, hi, lo);
        *(uint32_t*)(sraw + S_AH + e * 144 + kk * 2) = hi;
        *(uint32_t*)(sraw + S_AL + e * 144 + kk * 2) = lo;
    }
    __syncthreads();

    const uint32_t aoff1 = (lan & 15) * 144 + (lan >> 4) * 16;
    const uint32_t boff1 = (wid * 16 + (lan & 7)) * 144 + ((lan >> 3) & 1) * 16;
    const uint32_t aoff2 = (lan & 15) * 272 + (lan >> 4) * 16;
    const uint32_t boff2 = (wid * 16 + (lan & 7)) * 272 + ((lan >> 3) & 1) * 16;

    float acc[8][2][4];

    // layer 1
    #pragma unroll
    for (int mt = 0; mt < 8; mt++)
        #pragma unroll
        for (int nt = 0; nt < 2; nt++)
            #pragma unroll
            for (int i = 0; i < 4; i++) acc[mt][nt][i] = 0.f;
    {
        const uint32_t ab[3] = { sb + S_AH + aoff1, sb + S_AH + aoff1, sb + S_AL + aoff1 };
        const uint32_t bb[3] = { sb + S_W1H + boff1, sb + S_W1L + boff1, sb + S_W1H + boff1 };
        #pragma unroll 1
        for (int t = 0; t < 3; t++) {
            #pragma unroll 1
            for (int ks = 0; ks < 4; ks++) {
                uint32_t bf0[2], bf1[2];
                ldsm_x2(bf0, bb[t] + ks * 32);
                ldsm_x2(bf1, bb[t] + 8 * 144 + ks * 32);
                #pragma unroll
                for (int mt = 0; mt < 8; mt++) {
                    uint32_t af[4];
                    ldsm_x4(af, ab[t] + mt * (16 * 144) + ks * 32);
                    mma_bf16(acc[mt][0], af, bf0);
                    mma_bf16(acc[mt][1], af, bf1);
                }
            }
        }
    }
    __syncthreads();

    // epilogue 1: ssp(acc + b1) -> A2 hi/lo [128][136]
    {
        const int ch0 = wid * 16 + (lan & 3) * 2;
        const float bA0 = b1g[ch0],     bA1 = b1g[ch0 + 1];
        const float bA2 = b1g[ch0 + 8], bA3 = b1g[ch0 + 9];
        #pragma unroll
        for (int mt = 0; mt < 8; mt++) {
            int er = mt * 16 + (lan >> 2);
            uint32_t hi, lo;
            float v0 = sspf(acc[mt][0][0] + bA0), v1 = sspf(acc[mt][0][1] + bA1);
            bfsplit(v0, v1, hi, lo);
            *(uint32_t*)(sraw + S_AH + er * 272 + ch0 * 2) = hi;
            *(uint32_t*)(sraw + S_AL + er * 272 + ch0 * 2) = lo;
            float v2 = sspf(acc[mt][0][2] + bA0), v3 = sspf(acc[mt][0][3] + bA1);
            bfsplit(v2, v3, hi, lo);
            *(uint32_t*)(sraw + S_AH + (er + 8) * 272 + ch0 * 2) = hi;
            *(uint32_t*)(sraw + S_AL + (er + 8) * 272 + ch0 * 2) = lo;
            float v4 = sspf(acc[mt][1][0] + bA2), v5 = sspf(acc[mt][1][1] + bA3);
            bfsplit(v4, v5, hi, lo);
            *(uint32_t*)(sraw + S_AH + er * 272 + (ch0 + 8) * 2) = hi;
            *(uint32_t*)(sraw + S_AL + er * 272 + (ch0 + 8) * 2) = lo;
            float v6 = sspf(acc[mt][1][2] + bA2), v7 = sspf(acc[mt][1][3] + bA3);
            bfsplit(v6, v7, hi, lo);
            *(uint32_t*)(sraw + S_AH + (er + 8) * 272 + (ch0 + 8) * 2) = hi;
            *(uint32_t*)(sraw + S_AL + (er + 8) * 272 + (ch0 + 8) * 2) = lo;
        }
    }
    __syncthreads();

    // layer 2
    #pragma unroll
    for (int mt = 0; mt < 8; mt++)
        #pragma unroll
        for (int nt = 0; nt < 2; nt++)
            #pragma unroll
            for (int i = 0; i < 4; i++) acc[mt][nt][i] = 0.f;
    {
        const uint32_t ab[3] = { sb + S_AH + aoff2, sb + S_AH + aoff2, sb + S_AL + aoff2 };
        const uint32_t bb[3] = { sb + S_W2H + boff2, sb + S_W2L + boff2, sb + S_W2H + boff2 };
        #pragma unroll 1
        for (int t = 0; t < 3; t++) {
            #pragma unroll 1
            for (int ks = 0; ks < 8; ks++) {
                uint32_t bf0[2], bf1[2];
                ldsm_x2(bf0, bb[t] + ks * 32);
                ldsm_x2(bf1, bb[t] + 8 * 272 + ks * 32);
                #pragma unroll
                for (int mt = 0; mt < 8; mt++) {
                    uint32_t af[4];
                    ldsm_x4(af, ab[t] + mt * (16 * 272) + ks * 32);
                    mma_bf16(acc[mt][0], af, bf0);
                    mma_bf16(acc[mt][1], af, bf1);
                }
            }
        }
    }

    // epilogue 2: table[row][ch] = acc + b2  (fp16 table)
    {
        __half2* tbl = (__half2*)g_tableh[kblk];
        const int ch0 = wid * 16 + (lan & 3) * 2;   // even
        const int cp  = ch0 >> 1;
        const float bB0 = b2g[ch0],     bB1 = b2g[ch0 + 1];
        const float bB2 = b2g[ch0 + 8], bB3 = b2g[ch0 + 9];
        #pragma unroll
        for (int mt = 0; mt < 8; mt++) {
            int r0 = e0 + mt * 16 + (lan >> 2);
            int r1 = r0 + 8;
            tbl[r0 * 64 + cp]     = __floats2half2_rn(acc[mt][0][0] + bB0, acc[mt][0][1] + bB1);
            tbl[r1 * 64 + cp]     = __floats2half2_rn(acc[mt][0][2] + bB0, acc[mt][0][3] + bB1);
            tbl[r0 * 64 + cp + 4] = __floats2half2_rn(acc[mt][1][0] + bB2, acc[mt][1][1] + bB3);
            tbl[r1 * 64 + cp + 4] = __floats2half2_rn(acc[mt][1][2] + bB2, acc[mt][1][3] + bB3);
        }
    }
}

// ---------------- message + aggregate: CSR gather, fp16 table lerp ----------
__global__ void __launch_bounds__(256)
k_msg(int kblk) {
    const int wid = threadIdx.x >> 5;
    const int lan = threadIdx.x & 31;
    const int n = blockIdx.x * 8 + wid;
    if (n >= NODES) return;
    const int s = g_ptr[n], e = g_ptr[n + 1];
    const uint2* __restrict__ T = (const uint2*)g_tableh[kblk];   // 32 uint2/row
    const uint2* __restrict__ X = (const uint2*)g_xh;
    float4 acc = make_float4(0.f, 0.f, 0.f, 0.f);
    #pragma unroll 2
    for (int j = s; j < e; j++) {
        const int4 m = __ldg(&g_meta[j]);
        const float w0 = __int_as_float(m.z);
        const float w1 = __int_as_float(m.w);
        const uint2 xr = X[m.x * 32 + lan];
        const uint2 t0 = T[m.y * 32 + lan];
        const uint2 t1 = T[m.y * 32 + 32 + lan];
        float2 xa = __half22float2(*(const __half2*)&xr.x);
        float2 xb = __half22float2(*(const __half2*)&xr.y);
        float2 a0 = __half22float2(*(const __half2*)&t0.x);
        float2 a1 = __half22float2(*(const __half2*)&t0.y);
        float2 b0 = __half22float2(*(const __half2*)&t1.x);
        float2 b1 = __half22float2(*(const __half2*)&t1.y);
        acc.x += xa.x * (a0.x * w0 + b0.x * w1);
        acc.y += xa.y * (a0.y * w0 + b0.y * w1);
        acc.z += xb.x * (a1.x * w0 + b1.x * w1);
        acc.w += xb.y * (a1.y * w0 + b1.y * w1);
    }
    ((float4*)g_agg)[n * 32 + lan] = acc;
}

// ---------------- first node GEMM: xh = h @ cl1[0] ---------------------------
#define G0_SMEM ((16384 + NTILE * HIDC) * 4)
__global__ void __launch_bounds__(256)
k_gemm0(const float* __restrict__ W) {
    extern __shared__ unsigned char sraw[];
    float* Ws  = (float*)sraw;
    float* ins = Ws + HIDC * HIDC;

    const int tid = threadIdx.x;
    const int f   = tid & 127;
    const int grp = tid >> 7;
    const int n0  = blockIdx.x * NTILE;

    {
        const float4* g4 = (const float4*)W;
        float4* s4 = (float4*)Ws;
        #pragma unroll 4
        for (int i = tid; i < HIDC * HIDC / 4; i += 256) s4[i] = g4[i];
        const float4* ig = (const float4*)g_h;
        float4* is4 = (float4*)ins;
        for (int i = tid; i < NTILE * HIDC / 4; i += 256) {
            int n = n0 + (i >> 5);
            int nc = (n < NODES) ? n : NODES - 1;
            is4[i] = ig[nc * 32 + (i & 31)];
        }
    }
    __syncthreads();

    ull acc[NPG];
    #pragma unroll
    for (int e = 0; e < NPG; e++) acc[e] = pack2(0.f, 0.f);

    const int nb = grp * NPG;
    #pragma unroll 1
    for (int c = 0; c < HIDC; c += 4) {
        ull w01 = pack2(Ws[c * HIDC + f],       Ws[(c + 1) * HIDC + f]);
        ull w23 = pack2(Ws[(c + 2) * HIDC + f], Ws[(c + 3) * HIDC + f]);
        #pragma unroll
        for (int e = 0; e < NPG; e++) {
            ulonglong2 hv = *(const ulonglong2*)&ins[(nb + e) * HIDC + c];
            acc[e] = fma2(hv.x, w01, acc[e]);
            acc[e] = fma2(hv.y, w23, acc[e]);
        }
    }

    #pragma unroll
    for (int e = 0; e < NPG; e++) {
        int n = n0 + nb + e;
        if (n < NODES) {
            float a, b; unpack2(acc[e], a, b);
            g_xh[n * HIDC + f] = __float2half(a + b);
        }
    }
}

// ------ fused node GEMMs, cp.async double-buffered, SINGLE WAVE (139 CTAs) ---
// 512 threads, NPC=72 nodes/CTA: f2 = tid&63 owns {f2, f2+64}; grp = tid>>6
// owns GNP=9 nodes. Phases:
//   A: mid = ssp(agg @ W2 + b2)   [W0]   (prefetch Wl -> W1)
//   B: h  += mid @ Wl + bl        [W1]   (prefetch Wc -> W0)
//   C: xh  = h_new @ Wc (fp16)    [W0]
#define GF_SMEM ((16384 * 2 + NPC * HIDC) * 4)   // 167936 B

template <bool DO_C>
__global__ void __launch_bounds__(512, 1)
k_gfused(const float* __restrict__ W2, const float* __restrict__ b2v,
         const float* __restrict__ Wl, const float* __restrict__ blv,
         const float* __restrict__ Wc) {
    extern __shared__ __align__(16) unsigned char sraw[];
    float* W0   = (float*)sraw;                     // 64 KB
    float* W1   = W0 + 16384;                       // 64 KB
    float* data = W1 + 16384;                       // 36 KB
    const uint32_t sW0 = smem_u32(W0);
    const uint32_t sW1 = smem_u32(W1);
    const uint32_t sD  = smem_u32(data);

    const int tid = threadIdx.x;
    const int f2  = tid & 63;
    const int grp = tid >> 6;       // 0..7
    const int n0  = blockIdx.x * NPC;
    const int nb  = grp * GNP;

    // group 0: W2 + agg tile
    {
        uint64_t gw = __cvta_generic_to_global(W2);
        #pragma unroll
        for (int i = tid; i < 4096; i += 512) CP16(sW0 + i * 16, gw + i * 16);
        uint64_t ga = __cvta_generic_to_global(g_agg);
        for (int i = tid; i < NPC * 32; i += 512) {
            int n = n0 + (i >> 5);
            int nc = (n < NODES) ? n : NODES - 1;
            CP16(sD + i * 16, ga + (uint64_t)(nc * 32 + (i & 31)) * 16);
        }
    }
    CP_COMMIT();
    // group 1: Wl
    {
        uint64_t gw = __cvta_generic_to_global(Wl);
        #pragma unroll
        for (int i = tid; i < 4096; i += 512) CP16(sW1 + i * 16, gw + i * 16);
    }
    CP_COMMIT();

    const float b2a = b2v[f2],      b2b = b2v[f2 + 64];
    const float bla = blv[f2],      blb = blv[f2 + 64];

    CP_WAIT(1);          // group 0 (W2 + agg) complete
    __syncthreads();

    // ---- phase A: mid = ssp(agg @ W2 + b2) ----
    float mida[GNP], midb[GNP];
    {
        ull acc0[GNP], acc1[GNP];
        #pragma unroll
        for (int e = 0; e < GNP; e++) { acc0[e] = pack2(b2a, 0.f); acc1[e] = pack2(b2b, 0.f); }
        #pragma unroll 1
        for (int c = 0; c < HIDC; c += 4) {
            ull wa01 = pack2(W0[c * HIDC + f2],       W0[(c + 1) * HIDC + f2]);
            ull wa23 = pack2(W0[(c + 2) * HIDC + f2], W0[(c + 3) * HIDC + f2]);
            ull wb01 = pack2(W0[c * HIDC + f2 + 64],       W0[(c + 1) * HIDC + f2 + 64]);
            ull wb23 = pack2(W0[(c + 2) * HIDC + f2 + 64], W0[(c + 3) * HIDC + f2 + 64]);
            #pragma unroll
            for (int e = 0; e < GNP; e++) {
                ulonglong2 hv = *(const ulonglong2*)&data[(nb + e) * HIDC + c];
                acc0[e] = fma2(hv.x, wa01, acc0[e]);
                acc0[e] = fma2(hv.y, wa23, acc0[e]);
                acc1[e] = fma2(hv.x, wb01, acc1[e]);
                acc1[e] = fma2(hv.y, wb23, acc1[e]);
            }
        }
        #pragma unroll
        for (int e = 0; e < GNP; e++) {
            float a, b;
            unpack2(acc0[e], a, b); mida[e] = sspf(a + b);
            unpack2(acc1[e], a, b); midb[e] = sspf(a + b);
        }
    }
    __syncthreads();    // reads of W0/data done

    // data = mid ; prefetch Wc -> W0
    #pragma unroll
    for (int e = 0; e < GNP; e++) {
        data[(nb + e) * HIDC + f2]      = mida[e];
        data[(nb + e) * HIDC + f2 + 64] = midb[e];
    }
    if (DO_C) {
        uint64_t gw = __cvta_generic_to_global(Wc);
        #pragma unroll
        for (int i = tid; i < 4096; i += 512) CP16(sW0 + i * 16, gw + i * 16);
        CP_COMMIT();
        CP_WAIT(1);      // Wl complete
    } else {
        CP_WAIT(0);      // Wl complete
    }
    __syncthreads();

    // ---- phase B: h_new = h + mid @ Wl + bl ----
    float hna[GNP], hnb[GNP];
    {
        ull acc0[GNP], acc1[GNP];
        #pragma unroll
        for (int e = 0; e < GNP; e++) { acc0[e] = pack2(bla, 0.f); acc1[e] = pack2(blb, 0.f); }
        #pragma unroll 1
        for (int c = 0; c < HIDC; c += 4) {
            ull wa01 = pack2(W1[c * HIDC + f2],       W1[(c + 1) * HIDC + f2]);
            ull wa23 = pack2(W1[(c + 2) * HIDC + f2], W1[(c + 3) * HIDC + f2]);
            ull wb01 = pack2(W1[c * HIDC + f2 + 64],       W1[(c + 1) * HIDC + f2 + 64]);
            ull wb23 = pack2(W1[(c + 2) * HIDC + f2 + 64], W1[(c + 3) * HIDC + f2 + 64]);
            #pragma unroll
            for (int e = 0; e < GNP; e++) {
                ulonglong2 hv = *(const ulonglong2*)&data[(nb + e) * HIDC + c];
                acc0[e] = fma2(hv.x, wa01, acc0[e]);
                acc0[e] = fma2(hv.y, wa23, acc0[e]);
                acc1[e] = fma2(hv.x, wb01, acc1[e]);
                acc1[e] = fma2(hv.y, wb23, acc1[e]);
            }
        }
        #pragma unroll
        for (int e = 0; e < GNP; e++) {
            int n = n0 + nb + e;
            float a, b;
            unpack2(acc0[e], a, b);
            float h0 = (n < NODES) ? g_h[n * HIDC + f2] : 0.f;
            hna[e] = h0 + a + b;
            unpack2(acc1[e], a, b);
            float h1 = (n < NODES) ? g_h[n * HIDC + f2 + 64] : 0.f;
            hnb[e] = h1 + a + b;
            if (n < NODES) {
                g_h[n * HIDC + f2]      = hna[e];
                g_h[n * HIDC + f2 + 64] = hnb[e];
            }
        }
    }
    if (!DO_C) return;

    __syncthreads();    // phase B reads of data done

    // data = h_new
    #pragma unroll
    for (int e = 0; e < GNP; e++) {
        data[(nb + e) * HIDC + f2]      = hna[e];
        data[(nb + e) * HIDC + f2 + 64] = hnb[e];
    }
    CP_WAIT(0);          // Wc complete
    __syncthreads();

    // ---- phase C: xh = h_new @ Wc (fp16) ----
    {
        ull acc0[GNP], acc1[GNP];
        #pragma unroll
        for (int e = 0; e < GNP; e++) { acc0[e] = pack2(0.f, 0.f); acc1[e] = pack2(0.f, 0.f); }
        #pragma unroll 1
        for (int c = 0; c < HIDC; c += 4) {
            ull wa01 = pack2(W0[c * HIDC + f2],       W0[(c + 1) * HIDC + f2]);
            ull wa23 = pack2(W0[(c + 2) * HIDC + f2], W0[(c + 3) * HIDC + f2]);
            ull wb01 = pack2(W0[c * HIDC + f2 + 64],       W0[(c + 1) * HIDC + f2 + 64]);
            ull wb23 = pack2(W0[(c + 2) * HIDC + f2 + 64], W0[(c + 3) * HIDC + f2 + 64]);
            #pragma unroll
            for (int e = 0; e < GNP; e++) {
                ulonglong2 hv = *(const ulonglong2*)&data[(nb + e) * HIDC + c];
                acc0[e] = fma2(hv.x, wa01, acc0[e]);
                acc0[e] = fma2(hv.y, wa23, acc0[e]);
                acc1[e] = fma2(hv.x, wb01, acc1[e]);
                acc1[e] = fma2(hv.y, wb23, acc1[e]);
            }
        }
        #pragma unroll
        for (int e = 0; e < GNP; e++) {
            int n = n0 + nb + e;
            if (n < NODES) {
                float a, b;
                unpack2(acc0[e], a, b);
                g_xh[n * HIDC + f2]      = __float2half(a + b);
                unpack2(acc1[e], a, b);
                g_xh[n * HIDC + f2 + 64] = __float2half(a + b);
            }
        }
    }
}

// ---------------- output head ------------------------------------------------
__global__ void k_out(const float* __restrict__ w1, const float* __restrict__ b1,
                      const float* __restrict__ w2, const float* __restrict__ b2,
                      float* __restrict__ out) {
    __shared__ float hrow[HIDC];
    __shared__ float partial[2];
    const int n = blockIdx.x, j = threadIdx.x;   // blockDim = 64
    hrow[j]      = g_h[n * HIDC + j];
    hrow[j + 64] = g_h[n * HIDC + 64 + j];
    __syncthreads();
    float acc = b1[j];
    #pragma unroll 8
    for (int c = 0; c < HIDC; c++) acc += hrow[c] * w1[c * 64 + j];
    float s = sspf(acc) * w2[j];
    #pragma unroll
    for (int o = 16; o > 0; o >>= 1) s += __shfl_down_sync(0xffffffffu, s, o);
    if ((j & 31) == 0) partial[j >> 5] = s;
    __syncthreads();
    if (j == 0) out[n] = partial[0] + partial[1] + b2[0];
}

// ---------------- launcher ---------------------------------------------------
extern "C" void kernel_launch(void* const* d_in, const int* in_sizes, int n_in,
                              void* d_out, int out_size) {
    const int*   z    = (const int*)d_in[0];
    const float* pos  = (const float*)d_in[1];
    const int*   ei   = (const int*)d_in[2];
    const float* emb  = (const float*)d_in[3];
    const float* mw1  = (const float*)d_in[4];
    const float* mb1  = (const float*)d_in[5];
    const float* mw2  = (const float*)d_in[6];
    const float* mb2  = (const float*)d_in[7];
    const float* cl1  = (const float*)d_in[8];
    const float* cl2  = (const float*)d_in[9];
    const float* cl2b = (const float*)d_in[10];
    const float* lw   = (const float*)d_in[11];
    const float* lb   = (const float*)d_in[12];
    const float* ow1  = (const float*)d_in[13];
    const float* ob1  = (const float*)d_in[14];
    const float* ow2  = (const float*)d_in[15];
    const float* ob2  = (const float*)d_in[16];
    float* out = (float*)d_out;

    const int* row = ei;
    const int* col = ei + EDGES;

    cudaFuncSetAttribute(k_tbuild, cudaFuncAttributeMaxDynamicSharedMemorySize, FILT_SMEM);
    cudaFuncSetAttribute(k_gemm0,  cudaFuncAttributeMaxDynamicSharedMemorySize, G0_SMEM);
    cudaFuncSetAttribute(k_gfused<true>,  cudaFuncAttributeMaxDynamicSharedMemorySize, GF_SMEM);
    cudaFuncSetAttribute(k_gfused<false>, cudaFuncAttributeMaxDynamicSharedMemorySize, GF_SMEM);

    // one-time (per launch) prep
    k_wprep<<<NBLK, 256>>>(mw1, mw2);                    // also zeroes g_cnt
    k_embed<<<(NODES * HIDC + 255) / 256, 256>>>(z, emb, col);   // also CSR count
    k_scan<<<1, 1024>>>();
    k_fill<<<(EDGES + 255) / 256, 256>>>(pos, row, col);
    {
        dim3 tg(TROWS / 128, NBLK);
        k_tbuild<<<tg, 256, FILT_SMEM>>>(mb1, mb2);
    }

    const int g0grid = (NODES + NTILE - 1) / NTILE;
    const int gfgrid = (NODES + NPC - 1) / NPC;          // 139 <= 148: one wave
    const int mgrid  = (NODES + 7) / 8;

    k_gemm0<<<g0grid, 256, G0_SMEM>>>(cl1);

    for (int k = 0; k < NBLK; k++) {
        k_msg<<<mgrid, 256>>>(k);
        if (k < NBLK - 1) {
            k_gfused<true><<<gfgrid, 512, GF_SMEM>>>(
                cl2 + k * HIDC * HIDC, cl2b + k * HIDC,
                lw  + k * HIDC * HIDC, lb   + k * HIDC,
                cl1 + (k + 1) * HIDC * HIDC);
        } else {
            k_gfused<false><<<gfgrid, 512, GF_SMEM>>>(
                cl2 + k * HIDC * HIDC, cl2b + k * HIDC,
                lw  + k * HIDC * HIDC, lb   + k * HIDC, nullptr);
        }
    }

    k_out<<<NODES, 64>>>(ow1, ob1, ow2, ob2, out);
}